// round 1
// baseline (speedup 1.0000x reference)
#include <cuda_runtime.h>
#include <math.h>

#define IMG   512
#define OUTD  502
#define NIMG  96
#define TILE_W 118
#define TILE_H 16
#define GBX 5
#define GBY 32
#define NBLK (GBX * GBY * NIMG)   // 15360

// Gaussian(sigma=1.5, K=11) normalized weights, symmetric: W[k], k=0..10, W[5]=center
#define W0 0.00102839f
#define W1 0.00759864f
#define W2 0.03600077f
#define W3 0.10936070f
#define W4 0.21300553f
#define W5 0.26601172f

__device__ int   g_flags[2];
__device__ float g_partials[NBLK];

__global__ void k_init() {
    g_flags[0] = 0;
    g_flags[1] = 0;
}

// any(img1 > 128), any(img1 < -0.5)
__global__ void k_flags(const float4* __restrict__ x, int n4) {
    bool f1 = false, f2 = false;
    for (int i = blockIdx.x * blockDim.x + threadIdx.x; i < n4; i += gridDim.x * blockDim.x) {
        float4 v = x[i];
        f1 |= (v.x > 128.0f) | (v.y > 128.0f) | (v.z > 128.0f) | (v.w > 128.0f);
        f2 |= (v.x < -0.5f) | (v.y < -0.5f) | (v.z < -0.5f) | (v.w < -0.5f);
    }
    unsigned m1 = __ballot_sync(0xffffffffu, f1);
    unsigned m2 = __ballot_sync(0xffffffffu, f2);
    if ((threadIdx.x & 31) == 0) {
        if (m1) atomicOr(&g_flags[0], 1);
        if (m2) atomicOr(&g_flags[1], 1);
    }
}

__global__ __launch_bounds__(128)
void k_ssim(const float* __restrict__ img1, const float* __restrict__ img2) {
    // padded stride 136: phase-2 banks (8*y + 15*cg + i) mod 32 are all distinct -> conflict-free
    __shared__ float vs[5][TILE_H][136];

    const float W[11] = {W0, W1, W2, W3, W4, W5, W4, W3, W2, W1, W0};

    const int tid = threadIdx.x;
    const int bx = blockIdx.x, by = blockIdx.y, z = blockIdx.z;
    const float* p1 = img1 + (size_t)z * IMG * IMG;
    const float* p2 = img2 + (size_t)z * IMG * IMG;

    const int gx = bx * TILE_W + tid;           // column this thread owns in phase 1
    const bool colok = (gx < IMG);
    const int ybase = by * TILE_H;

    // ---------------- Phase 1: vertical 11-tap conv, sliding accumulators ----------------
    float acc[5][TILE_H];
#pragma unroll
    for (int q = 0; q < 5; q++)
#pragma unroll
        for (int r = 0; r < TILE_H; r++) acc[q][r] = 0.0f;

#pragma unroll
    for (int j = 0; j < TILE_H + 10; j++) {
        const int yin = ybase + j;
        float a = 0.0f, b = 0.0f;
        if (colok && yin < IMG) {
            a = p1[yin * IMG + gx];
            b = p2[yin * IMG + gx];
        }
        const float aa = a * a, bb = b * b, ab = a * b;
#pragma unroll
        for (int r = 0; r < TILE_H; r++) {
            const int k = j - r;
            if (k >= 0 && k < 11) {
                const float w = W[k];
                acc[0][r] += w * a;
                acc[1][r] += w * b;
                acc[2][r] += w * aa;
                acc[3][r] += w * bb;
                acc[4][r] += w * ab;
            }
        }
    }

#pragma unroll
    for (int q = 0; q < 5; q++)
#pragma unroll
        for (int r = 0; r < TILE_H; r++) vs[q][r][tid] = acc[q][r];

    __syncthreads();

    // ---------------- Phase 2: horizontal 11-tap conv, sliding window ----------------
    const int y  = tid >> 3;     // 0..15  output row within tile
    const int cg = tid & 7;      // 0..7   column group
    const int xs = cg * 15;      // covers local out cols xs..xs+14 (cg=7: only 13 valid)

    float o[5][15];
#pragma unroll
    for (int q = 0; q < 5; q++)
#pragma unroll
        for (int s = 0; s < 15; s++) o[q][s] = 0.0f;

#pragma unroll
    for (int q = 0; q < 5; q++) {
        float v[25];
#pragma unroll
        for (int i = 0; i < 25; i++) v[i] = vs[q][y][xs + i];  // xs+i <= 129 < 136 (extra feeds masked outputs only)
#pragma unroll
        for (int i = 0; i < 25; i++) {
#pragma unroll
            for (int s = 0; s < 15; s++) {
                const int k = i - s;
                if (k >= 0 && k < 11) o[q][s] += W[k] * v[i];
            }
        }
    }

    // ---------------- SSIM map + block-local sum ----------------
    const float maxv = g_flags[0] ? 255.0f : 1.0f;
    const float minv = g_flags[1] ? -1.0f : 0.0f;
    const float L  = maxv - minv;
    const float C1 = (0.01f * L) * (0.01f * L);
    const float C2 = (0.03f * L) * (0.03f * L);

    const int gy   = ybase + y;
    const int xlim = min(TILE_W, OUTD - bx * TILE_W);  // valid local out columns

    float lsum = 0.0f;
    if (gy < OUTD) {
#pragma unroll
        for (int s = 0; s < 15; s++) {
            const int x = xs + s;
            if (x < xlim) {
                const float mu1 = o[0][s], mu2 = o[1][s];
                const float mu1s = mu1 * mu1, mu2s = mu2 * mu2, mu12 = mu1 * mu2;
                const float s1  = o[2][s] - mu1s;
                const float s2  = o[3][s] - mu2s;
                const float s12 = o[4][s] - mu12;
                const float num = (2.0f * mu12 + C1) * (2.0f * s12 + C2);
                const float den = (mu1s + mu2s + C1) * (s1 + s2 + C2);
                lsum += __fdividef(num, den);
            }
        }
    }

    // block reduction
#pragma unroll
    for (int off = 16; off > 0; off >>= 1)
        lsum += __shfl_down_sync(0xffffffffu, lsum, off);

    __shared__ float warpsum[4];
    if ((tid & 31) == 0) warpsum[tid >> 5] = lsum;
    __syncthreads();
    if (tid == 0) {
        g_partials[bx + GBX * (by + GBY * z)] =
            warpsum[0] + warpsum[1] + warpsum[2] + warpsum[3];
    }
}

__global__ void k_final(float* __restrict__ out) {
    __shared__ double sm[256];
    double s = 0.0;
    for (int i = threadIdx.x; i < NBLK; i += 256) s += (double)g_partials[i];
    sm[threadIdx.x] = s;
    __syncthreads();
    for (int off = 128; off > 0; off >>= 1) {
        if (threadIdx.x < off) sm[threadIdx.x] += sm[threadIdx.x + off];
        __syncthreads();
    }
    if (threadIdx.x == 0) {
        const double cnt = (double)NIMG * OUTD * OUTD;
        out[0] = (float)(1.0 - sm[0] / cnt);
    }
}

extern "C" void kernel_launch(void* const* d_in, const int* in_sizes, int n_in,
                              void* d_out, int out_size) {
    const float* img1 = (const float*)d_in[0];
    const float* img2 = (const float*)d_in[1];
    float* out = (float*)d_out;

    k_init<<<1, 1>>>();
    k_flags<<<1024, 256>>>((const float4*)img1, (IMG * IMG * NIMG) / 4);
    dim3 grid(GBX, GBY, NIMG);
    k_ssim<<<grid, 128>>>(img1, img2);
    k_final<<<1, 256>>>(out);
}

// round 2
// speedup vs baseline: 1.0482x; 1.0482x over previous
#include <cuda_runtime.h>

#define IMG   512
#define OUTD  502
#define NIMG  96
#define TILE_W 118
#define TILE_H 16
#define GBX 5
#define GBY 32
#define NBLK (GBX * GBY * NIMG)   // 15360

// Gaussian(sigma=1.5, K=11) normalized weights
#define W0 0.00102839f
#define W1 0.00759864f
#define W2 0.03600077f
#define W3 0.10936070f
#define W4 0.21300553f
#define W5 0.26601172f

typedef unsigned long long u64;

// ---- packed f32x2 helpers (sm_100+) ----
#define PACK2(out, lo, hi) asm("mov.b64 %0, {%1, %2};" : "=l"(out) : "f"(lo), "f"(hi))
#define UNPACK2(lo, hi, in) asm("mov.b64 {%0, %1}, %2;" : "=f"(lo), "=f"(hi) : "l"(in))
#define FMA2(d, a, b, c) asm("fma.rn.f32x2 %0, %1, %2, %3;" : "=l"(d) : "l"(a), "l"(b), "l"(c))
#define MUL2(d, a, b)    asm("mul.rn.f32x2 %0, %1, %2;" : "=l"(d) : "l"(a), "l"(b))

__device__ int      g_flags[2];
__device__ unsigned g_count;
__device__ float    g_partials[NBLK];

__global__ void k_init() {
    g_flags[0] = 0;
    g_flags[1] = 0;
    g_count    = 0u;
}

// any(img1 > 128), any(img1 < -0.5)
__global__ void k_flags(const float4* __restrict__ x, int n4) {
    bool f1 = false, f2 = false;
    for (int i = blockIdx.x * blockDim.x + threadIdx.x; i < n4; i += gridDim.x * blockDim.x) {
        float4 v = x[i];
        f1 |= (v.x > 128.0f) | (v.y > 128.0f) | (v.z > 128.0f) | (v.w > 128.0f);
        f2 |= (v.x < -0.5f) | (v.y < -0.5f) | (v.z < -0.5f) | (v.w < -0.5f);
    }
    unsigned m1 = __ballot_sync(0xffffffffu, f1);
    unsigned m2 = __ballot_sync(0xffffffffu, f2);
    if ((threadIdx.x & 31) == 0) {
        if (m1) atomicOr(&g_flags[0], 1);
        if (m2) atomicOr(&g_flags[1], 1);
    }
}

// horizontal 11-tap conv over 25 packed inputs -> 15 packed outputs (sliding window)
__device__ __forceinline__ void hconv2(const u64* __restrict__ row, const u64* w2, u64* o) {
    u64 v[25];
#pragma unroll
    for (int i = 0; i < 25; i++) v[i] = row[i];
#pragma unroll
    for (int i = 0; i < 25; i++) {
#pragma unroll
        for (int s = 0; s < 15; s++) {
            const int k = i - s;
            if (k >= 0 && k < 11) FMA2(o[s], v[i], w2[k], o[s]);
        }
    }
}

__device__ __forceinline__ void hconv1(const float* __restrict__ row, const float* W, float* o) {
    float v[25];
#pragma unroll
    for (int i = 0; i < 25; i++) v[i] = row[i];
#pragma unroll
    for (int i = 0; i < 25; i++) {
#pragma unroll
        for (int s = 0; s < 15; s++) {
            const int k = i - s;
            if (k >= 0 && k < 11) o[s] = fmaf(W[k], v[i], o[s]);
        }
    }
}

__global__ __launch_bounds__(128)
void k_ssim(const float* __restrict__ img1, const float* __restrict__ img2,
            float* __restrict__ out) {
    // stride 136 keeps both 32-bit and 64-bit accesses bank-conflict-free
    __shared__ u64   s01[TILE_H][136];   // (mu1-acc, mu2-acc)
    __shared__ u64   s23[TILE_H][136];   // (x1^2-acc, x2^2-acc)
    __shared__ float s4 [TILE_H][136];   // x1*x2-acc
    __shared__ float warpsum[4];
    __shared__ int   s_last;
    __shared__ double red[4];

    const float Wf[11] = {W0, W1, W2, W3, W4, W5, W4, W3, W2, W1, W0};
    u64 w2[11];
#pragma unroll
    for (int k = 0; k < 11; k++) PACK2(w2[k], Wf[k], Wf[k]);

    const int tid = threadIdx.x;
    const int bx = blockIdx.x, by = blockIdx.y, z = blockIdx.z;
    const float* p1 = img1 + (size_t)z * IMG * IMG;
    const float* p2 = img2 + (size_t)z * IMG * IMG;

    const int gx = bx * TILE_W + tid;
    const bool colok = (gx < IMG);
    const int ybase = by * TILE_H;

    // ---------------- Phase 1: vertical 11-tap conv, packed sliding accumulators ----------------
    u64 acc01[TILE_H], acc23[TILE_H];
    float acc4[TILE_H];
#pragma unroll
    for (int r = 0; r < TILE_H; r++) { acc01[r] = 0ull; acc23[r] = 0ull; acc4[r] = 0.0f; }

#pragma unroll
    for (int j = 0; j < TILE_H + 10; j++) {
        const int yin = ybase + j;
        float a = 0.0f, b = 0.0f;
        if (colok && yin < IMG) {
            a = p1[yin * IMG + gx];
            b = p2[yin * IMG + gx];
        }
        u64 vab, vsq;
        PACK2(vab, a, b);
        MUL2(vsq, vab, vab);
        const float ab = a * b;
#pragma unroll
        for (int r = 0; r < TILE_H; r++) {
            const int k = j - r;
            if (k >= 0 && k < 11) {
                FMA2(acc01[r], vab, w2[k], acc01[r]);
                FMA2(acc23[r], vsq, w2[k], acc23[r]);
                acc4[r] = fmaf(ab, Wf[k], acc4[r]);
            }
        }
    }

#pragma unroll
    for (int r = 0; r < TILE_H; r++) {
        s01[r][tid] = acc01[r];
        s23[r][tid] = acc23[r];
        s4 [r][tid] = acc4[r];
    }
    __syncthreads();

    // ---------------- Phase 2: horizontal 11-tap conv, packed sliding window ----------------
    const int y  = tid >> 3;     // 0..15
    const int cg = tid & 7;      // 0..7
    const int xs = cg * 15;      // local out cols xs..xs+14

    u64 o01[15], o23[15];
    float o4[15];
#pragma unroll
    for (int s = 0; s < 15; s++) { o01[s] = 0ull; o23[s] = 0ull; o4[s] = 0.0f; }

    hconv2(&s01[y][xs], w2, o01);
    hconv2(&s23[y][xs], w2, o23);
    hconv1(&s4[y][xs], Wf, o4);

    // ---------------- SSIM map + block-local sum ----------------
    const float maxv = g_flags[0] ? 255.0f : 1.0f;
    const float minv = g_flags[1] ? -1.0f : 0.0f;
    const float L  = maxv - minv;
    const float C1 = (0.01f * L) * (0.01f * L);
    const float C2 = (0.03f * L) * (0.03f * L);

    const int gy   = ybase + y;
    const int xlim = min(TILE_W, OUTD - bx * TILE_W);

    float lsum = 0.0f;
    if (gy < OUTD) {
#pragma unroll
        for (int s = 0; s < 15; s++) {
            const int x = xs + s;
            if (x < xlim) {
                float mu1, mu2, e11, e22;
                UNPACK2(mu1, mu2, o01[s]);
                UNPACK2(e11, e22, o23[s]);
                const float mu1s = mu1 * mu1, mu2s = mu2 * mu2, mu12 = mu1 * mu2;
                const float s1  = e11 - mu1s;
                const float s2  = e22 - mu2s;
                const float s12 = o4[s] - mu12;
                const float num = (2.0f * mu12 + C1) * (2.0f * s12 + C2);
                const float den = (mu1s + mu2s + C1) * (s1 + s2 + C2);
                lsum += __fdividef(num, den);
            }
        }
    }

#pragma unroll
    for (int off = 16; off > 0; off >>= 1)
        lsum += __shfl_down_sync(0xffffffffu, lsum, off);

    if ((tid & 31) == 0) warpsum[tid >> 5] = lsum;
    __syncthreads();

    const int bid = bx + GBX * (by + GBY * z);
    if (tid == 0) {
        g_partials[bid] = warpsum[0] + warpsum[1] + warpsum[2] + warpsum[3];
        __threadfence();
        unsigned v = atomicAdd(&g_count, 1u);
        s_last = (v == NBLK - 1) ? 1 : 0;
    }
    __syncthreads();

    // ---------------- last block: final reduction ----------------
    if (s_last) {
        double s = 0.0;
        const int per = NBLK / 128;  // 120
#pragma unroll 4
        for (int i = 0; i < per; i++)
            s += (double)__ldcg(&g_partials[tid * per + i]);
#pragma unroll
        for (int off = 16; off > 0; off >>= 1)
            s += __shfl_down_sync(0xffffffffu, s, off);
        if ((tid & 31) == 0) red[tid >> 5] = s;
        __syncthreads();
        if (tid == 0) {
            const double cnt = (double)NIMG * OUTD * OUTD;
            out[0] = (float)(1.0 - (red[0] + red[1] + red[2] + red[3]) / cnt);
        }
    }
}

extern "C" void kernel_launch(void* const* d_in, const int* in_sizes, int n_in,
                              void* d_out, int out_size) {
    const float* img1 = (const float*)d_in[0];
    const float* img2 = (const float*)d_in[1];
    float* out = (float*)d_out;

    k_init<<<1, 1>>>();
    k_flags<<<2048, 256>>>((const float4*)img1, (IMG * IMG * NIMG) / 4);
    dim3 grid(GBX, GBY, NIMG);
    k_ssim<<<grid, 128>>>(img1, img2, out);
}